// round 16
// baseline (speedup 1.0000x reference)
#include <cuda_runtime.h>
#include <cuda_bf16.h>
#include <cstdint>

// TransINT scoring, single-pass quadratic form, DOUBLE-BUFFERED cp.async for
// the 4 entity rows (the DRAM-missing stream); heads/bases rows are served
// from L2 (high reuse) via regular LDG issued before the pipeline wait.
// Per warp: 4 grid-strided samples; while computing sample k, sample k+1's
// entity-row copies are in flight -> DRAM latency hidden behind compute.
//   re = heads[rel2head[r]] * rel2mult[r]        (r = pos_r; neg_r unused)
//   s_pos = ent[ph] + re - ent[pt];  s_neg = ent[nh] + re - ent[nt]
//   A = bases[r] (2 x 256); c = ATA^{-1} (A.s)
//   exact-solution identity: ||s - A^T c||^2 = s.s - c.(A.s)
// out[0:B) = pos, out[B:2B) = neg (float32)

#define D 256
#define WARPS_PER_BLOCK 4
#define SPW 4                       // samples per warp (grid-strided)
#define ROW_BYTES 1024              // 256 floats
#define STAGE_BYTES (4 * ROW_BYTES) // 4 entity rows per stage
// smem: 4 warps x 2 stages x 4KB = 32KB static

__device__ __forceinline__ uint32_t smem_u32(const void* p) {
    return (uint32_t)__cvta_generic_to_shared(p);
}
__device__ __forceinline__ void cp_async16(uint32_t dst, const void* src) {
    asm volatile("cp.async.cg.shared.global [%0], [%1], 16;"
                 :: "r"(dst), "l"(src));
}

__global__ __launch_bounds__(WARPS_PER_BLOCK * 32, 7)
void transint_kernel(const int* __restrict__ pos_h,
                     const int* __restrict__ pos_t,
                     const int* __restrict__ pos_r,
                     const int* __restrict__ neg_h,
                     const int* __restrict__ neg_t,
                     const float* __restrict__ ent_emb,   // E x D
                     const float* __restrict__ heads,     // K x D
                     const float* __restrict__ bases,     // R x 2 x D
                     const int* __restrict__ rel2head,
                     const float* __restrict__ rel2mult,
                     float* __restrict__ out,
                     int B)
{
    __shared__ __align__(16) char buf[WARPS_PER_BLOCK * 2 * STAGE_BYTES];

    const int warp = threadIdx.x >> 5;
    const int lane = threadIdx.x & 31;
    const int nw = gridDim.x * WARPS_PER_BLOCK;
    int s = blockIdx.x * WARPS_PER_BLOCK + warp;
    if (s >= B) return;

    char* wbuf = buf + warp * 2 * STAGE_BYTES;

    // Stage sample s's 4 entity rows into buffer 0.
    // Lane L copies float4 L and L+32 of each 1KB row (2 x 16B per row).
    {
        const float* e0 = ent_emb + (size_t)pos_h[s] * D;
        const float* e1 = ent_emb + (size_t)pos_t[s] * D;
        const float* e2 = ent_emb + (size_t)neg_h[s] * D;
        const float* e3 = ent_emb + (size_t)neg_t[s] * D;
        const uint32_t sb = smem_u32(wbuf);
        cp_async16(sb + 0*ROW_BYTES + lane*16,       e0 + lane*4);
        cp_async16(sb + 0*ROW_BYTES + 512 + lane*16, e0 + 128 + lane*4);
        cp_async16(sb + 1*ROW_BYTES + lane*16,       e1 + lane*4);
        cp_async16(sb + 1*ROW_BYTES + 512 + lane*16, e1 + 128 + lane*4);
        cp_async16(sb + 2*ROW_BYTES + lane*16,       e2 + lane*4);
        cp_async16(sb + 2*ROW_BYTES + 512 + lane*16, e2 + 128 + lane*4);
        cp_async16(sb + 3*ROW_BYTES + lane*16,       e3 + lane*4);
        cp_async16(sb + 3*ROW_BYTES + 512 + lane*16, e3 + 128 + lane*4);
        asm volatile("cp.async.commit_group;");
    }

    #pragma unroll 1
    for (int k = 0; k < SPW && s < B; ++k) {
        const int snext = s + nw;
        const bool has_next = (k + 1 < SPW) && (snext < B);

        // Sample k's relation rows: L2-resident, regular LDG, issued early
        const int r  = pos_r[s];
        const int hd = rel2head[r];
        const float mult = rel2mult[r];
        const float4* __restrict__ Hd  = (const float4*)(heads + (size_t)hd * D);
        const float4* __restrict__ A0p = (const float4*)(bases + (size_t)r * 2 * D);
        const float4* __restrict__ A1p = (const float4*)(bases + (size_t)r * 2 * D + D);
        float4 re0 = Hd[lane],  re1 = Hd[lane + 32];
        float4 a00 = A0p[lane], a01 = A0p[lane + 32];
        float4 a10 = A1p[lane], a11 = A1p[lane + 32];

        // Kick off sample k+1's entity rows into the other buffer
        if (has_next) {
            const float* e0 = ent_emb + (size_t)pos_h[snext] * D;
            const float* e1 = ent_emb + (size_t)pos_t[snext] * D;
            const float* e2 = ent_emb + (size_t)neg_h[snext] * D;
            const float* e3 = ent_emb + (size_t)neg_t[snext] * D;
            const uint32_t sb = smem_u32(wbuf + ((k + 1) & 1) * STAGE_BYTES);
            cp_async16(sb + 0*ROW_BYTES + lane*16,       e0 + lane*4);
            cp_async16(sb + 0*ROW_BYTES + 512 + lane*16, e0 + 128 + lane*4);
            cp_async16(sb + 1*ROW_BYTES + lane*16,       e1 + lane*4);
            cp_async16(sb + 1*ROW_BYTES + 512 + lane*16, e1 + 128 + lane*4);
            cp_async16(sb + 2*ROW_BYTES + lane*16,       e2 + lane*4);
            cp_async16(sb + 2*ROW_BYTES + 512 + lane*16, e2 + 128 + lane*4);
            cp_async16(sb + 3*ROW_BYTES + lane*16,       e3 + lane*4);
            cp_async16(sb + 3*ROW_BYTES + 512 + lane*16, e3 + 128 + lane*4);
            asm volatile("cp.async.commit_group;");
            asm volatile("cp.async.wait_group 1;" ::: "memory");  // sample k ready
        } else {
            asm volatile("cp.async.wait_group 0;" ::: "memory");
        }

        // Read back sample k's entity rows (each lane reads its own chunks)
        const float4* w4 = (const float4*)(wbuf + (k & 1) * STAGE_BYTES);
        float4 hp0 = w4[0*64 + lane], hp1 = w4[0*64 + 32 + lane];
        float4 tp0 = w4[1*64 + lane], tp1 = w4[1*64 + 32 + lane];
        float4 hn0 = w4[2*64 + lane], hn1 = w4[2*64 + 32 + lane];
        float4 tn0 = w4[3*64 + lane], tn1 = w4[3*64 + 32 + lane];

        // 9 streamed accumulators; single pass
        float aa = 0.f, ab = 0.f, dd = 0.f;
        float as0p = 0.f, as1p = 0.f, ssp = 0.f;
        float as0n = 0.f, as1n = 0.f, ssn = 0.f;
        {
            const float* hpp = (const float*)&hp0; const float* hpq = (const float*)&hp1;
            const float* tpp = (const float*)&tp0; const float* tpq = (const float*)&tp1;
            const float* hnp = (const float*)&hn0; const float* hnq = (const float*)&hn1;
            const float* tnp = (const float*)&tn0; const float* tnq = (const float*)&tn1;
            const float* rep = (const float*)&re0; const float* req = (const float*)&re1;
            const float* a0p = (const float*)&a00; const float* a0q = (const float*)&a01;
            const float* a1p = (const float*)&a10; const float* a1q = (const float*)&a11;
            #pragma unroll
            for (int i = 0; i < 4; i++) {
                {
                    const float re = rep[i] * mult;
                    const float sv = hpp[i] + re - tpp[i];
                    const float nv = hnp[i] + re - tnp[i];
                    const float A0 = a0p[i], A1 = a1p[i];
                    aa   = fmaf(A0, A0, aa);
                    ab   = fmaf(A0, A1, ab);
                    dd   = fmaf(A1, A1, dd);
                    as0p = fmaf(A0, sv, as0p);
                    as1p = fmaf(A1, sv, as1p);
                    ssp  = fmaf(sv, sv, ssp);
                    as0n = fmaf(A0, nv, as0n);
                    as1n = fmaf(A1, nv, as1n);
                    ssn  = fmaf(nv, nv, ssn);
                }
                {
                    const float re = req[i] * mult;
                    const float sv = hpq[i] + re - tpq[i];
                    const float nv = hnq[i] + re - tnq[i];
                    const float A0 = a0q[i], A1 = a1q[i];
                    aa   = fmaf(A0, A0, aa);
                    ab   = fmaf(A0, A1, ab);
                    dd   = fmaf(A1, A1, dd);
                    as0p = fmaf(A0, sv, as0p);
                    as1p = fmaf(A1, sv, as1p);
                    ssp  = fmaf(sv, sv, ssp);
                    as0n = fmaf(A0, nv, as0n);
                    as1n = fmaf(A1, nv, as1n);
                    ssn  = fmaf(nv, nv, ssn);
                }
            }
        }

        // Fused butterfly allreduce of 9 scalars
        #pragma unroll
        for (int m = 16; m > 0; m >>= 1) {
            aa   += __shfl_xor_sync(0xffffffffu, aa,   m);
            ab   += __shfl_xor_sync(0xffffffffu, ab,   m);
            dd   += __shfl_xor_sync(0xffffffffu, dd,   m);
            as0p += __shfl_xor_sync(0xffffffffu, as0p, m);
            as1p += __shfl_xor_sync(0xffffffffu, as1p, m);
            ssp  += __shfl_xor_sync(0xffffffffu, ssp,  m);
            as0n += __shfl_xor_sync(0xffffffffu, as0n, m);
            as1n += __shfl_xor_sync(0xffffffffu, as1n, m);
            ssn  += __shfl_xor_sync(0xffffffffu, ssn,  m);
        }

        if (lane == 0) {
            const float det = aa * dd - ab * ab;
            float scp, scn;
            if (det != 0.0f) {
                // exact normal-equation solve -> ||proj||^2 = ss - c . As
                const float inv_det = 1.0f / det;
                const float c0p = ( dd * as0p - ab * as1p) * inv_det;
                const float c1p = (-ab * as0p + aa * as1p) * inv_det;
                const float c0n = ( dd * as0n - ab * as1n) * inv_det;
                const float c1n = (-ab * as0n + aa * as1n) * inv_det;
                scp = ssp - c0p * as0p - c1p * as1p;
                scn = ssn - c0n * as0n - c1n * as1n;
            } else {
                // fallback c = As / aa is NOT the exact solution -> full quadratic
                const float inv_a = 1.0f / aa;
                const float c0p = as0p * inv_a, c1p = as1p * inv_a;
                const float c0n = as0n * inv_a, c1n = as1n * inv_a;
                scp = ssp - 2.0f * (c0p * as0p + c1p * as1p)
                    + c0p * c0p * aa + 2.0f * c0p * c1p * ab + c1p * c1p * dd;
                scn = ssn - 2.0f * (c0n * as0n + c1n * as1n)
                    + c0n * c0n * aa + 2.0f * c0n * c1n * ab + c1n * c1n * dd;
            }
            out[s]     = scp;
            out[B + s] = scn;
        }

        s = snext;
    }
}

extern "C" void kernel_launch(void* const* d_in, const int* in_sizes, int n_in,
                              void* d_out, int out_size) {
    const int*   pos_h    = (const int*)  d_in[0];
    const int*   pos_t    = (const int*)  d_in[1];
    const int*   pos_r    = (const int*)  d_in[2];
    const int*   neg_h    = (const int*)  d_in[3];
    const int*   neg_t    = (const int*)  d_in[4];
    // d_in[5] = neg_r (unused by the reference)
    const float* ent_emb  = (const float*)d_in[6];
    const float* heads    = (const float*)d_in[7];
    const float* bases    = (const float*)d_in[8];
    const int*   rel2head = (const int*)  d_in[9];
    const float* rel2mult = (const float*)d_in[10];
    float* out = (float*)d_out;

    const int B = in_sizes[0];
    const int total_warps = (B + SPW - 1) / SPW;
    const int blocks = (total_warps + WARPS_PER_BLOCK - 1) / WARPS_PER_BLOCK;
    transint_kernel<<<blocks, WARPS_PER_BLOCK * 32>>>(
        pos_h, pos_t, pos_r, neg_h, neg_t,
        ent_emb, heads, bases, rel2head, rel2mult, out, B);
}

// round 17
// speedup vs baseline: 1.1905x; 1.1905x over previous
#include <cuda_runtime.h>
#include <cuda_bf16.h>

// TransINT scoring, single-pass quadratic form (best measured config, R3):
//   re = heads[rel2head[r]] * rel2mult[r]        (r = pos_r; neg_r unused)
//   s_pos = ent[ph] + re - ent[pt];  s_neg = ent[nh] + re - ent[nt]
//   A = bases[r] (2 x 256); c = ATA^{-1} (A.s)
//   exact-solution identity: ||s - A^T c||^2 = s.s - c.(A.s)
// out[0:B) = pos, out[B:2B) = neg (float32)
//
// Design points (each validated against measured alternatives):
//  - 1 warp/sample; lane L owns float4 indices L and L+32 (contiguous 512B
//    warp accesses = minimal L1tex wavefronts).
//  - Single pass: 9 streamed FMA accumulators; ||proj||^2 computed from the
//    reduced scalars via the normal-equation identity (no data re-read).
//  - occ-5 hint -> 48-reg schedule (40 warps/SM); measured optimum vs
//    occ-4/64-reg, 2-warp/sample, cp.async staging/pipelining, LDG.256,
//    L2 evict_last, and software prefetch variants.

#define D 256
#define WARPS_PER_BLOCK 8

__global__ __launch_bounds__(WARPS_PER_BLOCK * 32, 5)
void transint_kernel(const int* __restrict__ pos_h,
                     const int* __restrict__ pos_t,
                     const int* __restrict__ pos_r,
                     const int* __restrict__ neg_h,
                     const int* __restrict__ neg_t,
                     const float* __restrict__ ent_emb,   // E x D
                     const float* __restrict__ heads,     // K x D
                     const float* __restrict__ bases,     // R x 2 x D
                     const int* __restrict__ rel2head,
                     const float* __restrict__ rel2mult,
                     float* __restrict__ out,
                     int B)
{
    const int warp = blockIdx.x * WARPS_PER_BLOCK + (threadIdx.x >> 5);
    if (warp >= B) return;
    const int lane = threadIdx.x & 31;

    // Per-sample indices (uniform across warp; broadcast loads)
    const int ph = pos_h[warp];
    const int pt = pos_t[warp];
    const int r  = pos_r[warp];
    const int nh = neg_h[warp];
    const int nt = neg_t[warp];
    const int hd = rel2head[r];
    const float mult = rel2mult[r];

    // Contiguous split: float4 index = lane and lane+32
    const int v0 = lane;
    const int v1 = lane + 32;

    const float4* __restrict__ Eph = (const float4*)(ent_emb + (size_t)ph * D);
    const float4* __restrict__ Ept = (const float4*)(ent_emb + (size_t)pt * D);
    const float4* __restrict__ Enh = (const float4*)(ent_emb + (size_t)nh * D);
    const float4* __restrict__ Ent = (const float4*)(ent_emb + (size_t)nt * D);
    const float4* __restrict__ Hd  = (const float4*)(heads   + (size_t)hd * D);
    const float4* __restrict__ A0p = (const float4*)(bases   + (size_t)r * 2 * D);
    const float4* __restrict__ A1p = (const float4*)(bases   + (size_t)r * 2 * D + D);

    // All 14 loads issued up-front (MLP covers L2/DRAM latency)
    float4 hp0 = Eph[v0], hp1 = Eph[v1];
    float4 tp0 = Ept[v0], tp1 = Ept[v1];
    float4 hn0 = Enh[v0], hn1 = Enh[v1];
    float4 tn0 = Ent[v0], tn1 = Ent[v1];
    float4 re0 = Hd[v0],  re1 = Hd[v1];
    float4 a00 = A0p[v0], a01 = A0p[v1];
    float4 a10 = A1p[v0], a11 = A1p[v1];

    // 9 streamed accumulators; no second pass over the data
    float aa = 0.f, ab = 0.f, dd = 0.f;
    float as0p = 0.f, as1p = 0.f, ssp = 0.f;
    float as0n = 0.f, as1n = 0.f, ssn = 0.f;

    {
        const float* hpp = (const float*)&hp0; const float* hpq = (const float*)&hp1;
        const float* tpp = (const float*)&tp0; const float* tpq = (const float*)&tp1;
        const float* hnp = (const float*)&hn0; const float* hnq = (const float*)&hn1;
        const float* tnp = (const float*)&tn0; const float* tnq = (const float*)&tn1;
        const float* rep = (const float*)&re0; const float* req = (const float*)&re1;
        const float* a0p = (const float*)&a00; const float* a0q = (const float*)&a01;
        const float* a1p = (const float*)&a10; const float* a1q = (const float*)&a11;
        #pragma unroll
        for (int i = 0; i < 4; i++) {
            {
                const float re = rep[i] * mult;
                const float sv = hpp[i] + re - tpp[i];
                const float nv = hnp[i] + re - tnp[i];
                const float A0 = a0p[i], A1 = a1p[i];
                aa   = fmaf(A0, A0, aa);
                ab   = fmaf(A0, A1, ab);
                dd   = fmaf(A1, A1, dd);
                as0p = fmaf(A0, sv, as0p);
                as1p = fmaf(A1, sv, as1p);
                ssp  = fmaf(sv, sv, ssp);
                as0n = fmaf(A0, nv, as0n);
                as1n = fmaf(A1, nv, as1n);
                ssn  = fmaf(nv, nv, ssn);
            }
            {
                const float re = req[i] * mult;
                const float sv = hpq[i] + re - tpq[i];
                const float nv = hnq[i] + re - tnq[i];
                const float A0 = a0q[i], A1 = a1q[i];
                aa   = fmaf(A0, A0, aa);
                ab   = fmaf(A0, A1, ab);
                dd   = fmaf(A1, A1, dd);
                as0p = fmaf(A0, sv, as0p);
                as1p = fmaf(A1, sv, as1p);
                ssp  = fmaf(sv, sv, ssp);
                as0n = fmaf(A0, nv, as0n);
                as1n = fmaf(A1, nv, as1n);
                ssn  = fmaf(nv, nv, ssn);
            }
        }
    }

    // Fused butterfly allreduce of 9 scalars
    #pragma unroll
    for (int m = 16; m > 0; m >>= 1) {
        aa   += __shfl_xor_sync(0xffffffffu, aa,   m);
        ab   += __shfl_xor_sync(0xffffffffu, ab,   m);
        dd   += __shfl_xor_sync(0xffffffffu, dd,   m);
        as0p += __shfl_xor_sync(0xffffffffu, as0p, m);
        as1p += __shfl_xor_sync(0xffffffffu, as1p, m);
        ssp  += __shfl_xor_sync(0xffffffffu, ssp,  m);
        as0n += __shfl_xor_sync(0xffffffffu, as0n, m);
        as1n += __shfl_xor_sync(0xffffffffu, as1n, m);
        ssn  += __shfl_xor_sync(0xffffffffu, ssn,  m);
    }

    if (lane == 0) {
        const float det = aa * dd - ab * ab;
        float scp, scn;
        if (det != 0.0f) {
            // exact normal-equation solve -> ||proj||^2 = ss - c . As
            const float inv_det = 1.0f / det;
            const float c0p = ( dd * as0p - ab * as1p) * inv_det;
            const float c1p = (-ab * as0p + aa * as1p) * inv_det;
            const float c0n = ( dd * as0n - ab * as1n) * inv_det;
            const float c1n = (-ab * as0n + aa * as1n) * inv_det;
            scp = ssp - c0p * as0p - c1p * as1p;
            scn = ssn - c0n * as0n - c1n * as1n;
        } else {
            // fallback c = As / aa is NOT the exact solution -> full quadratic
            const float inv_a = 1.0f / aa;
            const float c0p = as0p * inv_a, c1p = as1p * inv_a;
            const float c0n = as0n * inv_a, c1n = as1n * inv_a;
            scp = ssp - 2.0f * (c0p * as0p + c1p * as1p)
                + c0p * c0p * aa + 2.0f * c0p * c1p * ab + c1p * c1p * dd;
            scn = ssn - 2.0f * (c0n * as0n + c1n * as1n)
                + c0n * c0n * aa + 2.0f * c0n * c1n * ab + c1n * c1n * dd;
        }
        out[warp]     = scp;
        out[B + warp] = scn;
    }
}

extern "C" void kernel_launch(void* const* d_in, const int* in_sizes, int n_in,
                              void* d_out, int out_size) {
    const int*   pos_h    = (const int*)  d_in[0];
    const int*   pos_t    = (const int*)  d_in[1];
    const int*   pos_r    = (const int*)  d_in[2];
    const int*   neg_h    = (const int*)  d_in[3];
    const int*   neg_t    = (const int*)  d_in[4];
    // d_in[5] = neg_r (unused by the reference)
    const float* ent_emb  = (const float*)d_in[6];
    const float* heads    = (const float*)d_in[7];
    const float* bases    = (const float*)d_in[8];
    const int*   rel2head = (const int*)  d_in[9];
    const float* rel2mult = (const float*)d_in[10];
    float* out = (float*)d_out;

    const int B = in_sizes[0];
    const int blocks = (B + WARPS_PER_BLOCK - 1) / WARPS_PER_BLOCK;
    transint_kernel<<<blocks, WARPS_PER_BLOCK * 32>>>(
        pos_h, pos_t, pos_r, neg_h, neg_t,
        ent_emb, heads, bases, rel2head, rel2mult, out, B);
}